// round 16
// baseline (speedup 1.0000x reference)
#include <cuda_runtime.h>
#include <math_constants.h>

#define NB    4
#define MSEQ  2048
#define CDIM  512
#define HNUM  8
#define DHEAD 64
#define TOPK  16
#define BH    (NB * HNUM)   // 32 head-batches
#define KSPLIT 4
#define KSEG   (MSEQ / KSPLIT)  // 512 keys per split

// ---------------- scratch (static device globals; no allocation) ----------------
__device__ float g_xp[NB * MSEQ * CDIM];     // conv+residual output (16 MB)
__device__ float g_q[BH * MSEQ * DHEAD];     // per-head Q
__device__ float g_k[BH * MSEQ * DHEAD];     // per-head K
__device__ float g_v[BH * MSEQ * DHEAD];     // per-head V
__device__ float g_attn[NB * MSEQ * CDIM];   // attention output, (n,m,c) layout
__device__ float g_pvals[BH * MSEQ * KSPLIT * TOPK];  // partial top-k vals (sorted asc)
__device__ int   g_pinds[BH * MSEQ * KSPLIT * TOPK];  // partial top-k global key idx

// ---------------- packed f32x2 helpers (FFMA2: 2x fp32 throughput, sm_103a) ----
__device__ __forceinline__ unsigned long long ffma2(unsigned long long a,
                                                    unsigned long long b,
                                                    unsigned long long c) {
    unsigned long long d;
    asm("fma.rn.f32x2 %0, %1, %2, %3;" : "=l"(d) : "l"(a), "l"(b), "l"(c));
    return d;
}
__device__ __forceinline__ unsigned long long fadd2(unsigned long long a,
                                                    unsigned long long b) {
    unsigned long long d;
    asm("add.rn.f32x2 %0, %1, %2;" : "=l"(d) : "l"(a), "l"(b));
    return d;
}
__device__ __forceinline__ unsigned long long pack2(float lo, float hi) {
    unsigned long long r;
    asm("mov.b64 %0, {%1, %2};" : "=l"(r) : "f"(lo), "f"(hi));
    return r;
}
__device__ __forceinline__ unsigned long long dup2(float a) {
    unsigned long long r;
    asm("mov.b64 %0, {%1, %1};" : "=l"(r) : "f"(a));
    return r;
}
__device__ __forceinline__ float2 unpack2(unsigned long long v) {
    float2 f;
    asm("mov.b64 {%0, %1}, %2;" : "=f"(f.x), "=f"(f.y) : "l"(v));
    return f;
}

// ---------------- K0: dummy — shifts the ncu capture window (4th launch) onto
// route_part_kernel so the next round finally gets route's profile. -----------
__global__ void profile_shift_dummy_kernel() {}

// ---------------- K1: depthwise conv (k=3, SAME) + residual --------------------
__global__ void conv_res_kernel(const float* __restrict__ x,
                                const float* __restrict__ w,
                                const float* __restrict__ b) {
    int c = threadIdx.x;
    int m = blockIdx.x & (MSEQ - 1);
    int n = blockIdx.x >> 11;
    const float* base = x + ((size_t)(n * MSEQ + m)) * CDIM + c;
    float xc = base[0];
    float xl = (m > 0)        ? base[-CDIM] : 0.f;
    float xr = (m < MSEQ - 1) ? base[ CDIM] : 0.f;
    float w0 = w[3 * c], w1 = w[3 * c + 1], w2 = w[3 * c + 2];
    g_xp[((size_t)(n * MSEQ + m)) * CDIM + c] =
        xc + w0 * xl + w1 * xc + w2 * xr + b[c];
}

// ---------------- K2: QKV GEMM, 128x128 tiles, double-buffered -----------------
__global__ void __launch_bounds__(256) sgemm_qkv_kernel(const float* __restrict__ B,
                                                        const float* __restrict__ bias) {
    constexpr int NDIM = 3 * CDIM;
    __shared__ __align__(16) float As[2][16][128];
    __shared__ __align__(16) float Bs[2][16][128];

    int tid = threadIdx.x;
    int bm = blockIdx.y, bn = blockIdx.x;
    int rowBase = (tid >> 4) << 3;
    int colBase = (tid & 15) << 3;

    int ar = tid >> 2, ak = (tid & 3) << 2;
    int br = tid >> 5, bc = (tid & 31) << 2;

    const float* Ap = g_xp + ((size_t)(bm * 128)) * CDIM;
    const float* Bp = B + bn * 128;

    float4 a0 = *(const float4*)(Ap + (size_t)ar * CDIM + ak);
    float4 a1 = *(const float4*)(Ap + (size_t)(ar + 64) * CDIM + ak);
    float4 b0 = *(const float4*)(Bp + (size_t)br * NDIM + bc);
    float4 b1 = *(const float4*)(Bp + (size_t)(br + 8) * NDIM + bc);

    As[0][ak + 0][ar] = a0.x; As[0][ak + 1][ar] = a0.y;
    As[0][ak + 2][ar] = a0.z; As[0][ak + 3][ar] = a0.w;
    As[0][ak + 0][ar + 64] = a1.x; As[0][ak + 1][ar + 64] = a1.y;
    As[0][ak + 2][ar + 64] = a1.z; As[0][ak + 3][ar + 64] = a1.w;
    *(float4*)&Bs[0][br][bc] = b0;
    *(float4*)&Bs[0][br + 8][bc] = b1;
    __syncthreads();

    unsigned long long acc[8][4];
#pragma unroll
    for (int i = 0; i < 8; i++)
#pragma unroll
        for (int j = 0; j < 4; j++) acc[i][j] = 0ull;

#pragma unroll 1
    for (int kt = 0; kt < 31; kt++) {
        int cur = kt & 1, nxt = cur ^ 1;
        const float* Ak = Ap + (kt + 1) * 16;
        a0 = *(const float4*)(Ak + (size_t)ar * CDIM + ak);
        a1 = *(const float4*)(Ak + (size_t)(ar + 64) * CDIM + ak);
        const float* Bk = Bp + (size_t)((kt + 1) * 16) * NDIM;
        b0 = *(const float4*)(Bk + (size_t)br * NDIM + bc);
        b1 = *(const float4*)(Bk + (size_t)(br + 8) * NDIM + bc);

#pragma unroll
        for (int k = 0; k < 16; k++) {
            float4 av0 = *(const float4*)&As[cur][k][rowBase];
            float4 av1 = *(const float4*)&As[cur][k][rowBase + 4];
            ulonglong2 bv0 = *(const ulonglong2*)&Bs[cur][k][colBase];
            ulonglong2 bv1 = *(const ulonglong2*)&Bs[cur][k][colBase + 4];
            float af[8] = {av0.x, av0.y, av0.z, av0.w, av1.x, av1.y, av1.z, av1.w};
#pragma unroll
            for (int i = 0; i < 8; i++) {
                unsigned long long aa = dup2(af[i]);
                acc[i][0] = ffma2(aa, bv0.x, acc[i][0]);
                acc[i][1] = ffma2(aa, bv0.y, acc[i][1]);
                acc[i][2] = ffma2(aa, bv1.x, acc[i][2]);
                acc[i][3] = ffma2(aa, bv1.y, acc[i][3]);
            }
        }
        As[nxt][ak + 0][ar] = a0.x; As[nxt][ak + 1][ar] = a0.y;
        As[nxt][ak + 2][ar] = a0.z; As[nxt][ak + 3][ar] = a0.w;
        As[nxt][ak + 0][ar + 64] = a1.x; As[nxt][ak + 1][ar + 64] = a1.y;
        As[nxt][ak + 2][ar + 64] = a1.z; As[nxt][ak + 3][ar + 64] = a1.w;
        *(float4*)&Bs[nxt][br][bc] = b0;
        *(float4*)&Bs[nxt][br + 8][bc] = b1;
        __syncthreads();
    }
#pragma unroll
    for (int k = 0; k < 16; k++) {
        float4 av0 = *(const float4*)&As[1][k][rowBase];
        float4 av1 = *(const float4*)&As[1][k][rowBase + 4];
        ulonglong2 bv0 = *(const ulonglong2*)&Bs[1][k][colBase];
        ulonglong2 bv1 = *(const ulonglong2*)&Bs[1][k][colBase + 4];
        float af[8] = {av0.x, av0.y, av0.z, av0.w, av1.x, av1.y, av1.z, av1.w};
#pragma unroll
        for (int i = 0; i < 8; i++) {
            unsigned long long aa = dup2(af[i]);
            acc[i][0] = ffma2(aa, bv0.x, acc[i][0]);
            acc[i][1] = ffma2(aa, bv0.y, acc[i][1]);
            acc[i][2] = ffma2(aa, bv1.x, acc[i][2]);
            acc[i][3] = ffma2(aa, bv1.y, acc[i][3]);
        }
    }

    int co0 = bn * 128 + colBase;
    float bv[8];
#pragma unroll
    for (int j = 0; j < 8; j++) bv[j] = bias[co0 + j];

    int sec = co0 >> 9;            // 0:q 1:k 2:v
    int c2 = co0 & 511;
    int h = c2 >> 6, dd = c2 & 63;
    float* dstbuf = (sec == 0) ? g_q : (sec == 1) ? g_k : g_v;
#pragma unroll
    for (int i = 0; i < 8; i++) {
        int r = bm * 128 + rowBase + i;
        int n = r >> 11, mm = r & 2047;
        float* dst = dstbuf + ((size_t)((n * HNUM + h) * MSEQ + mm)) * DHEAD + dd;
        float2 p0 = unpack2(acc[i][0]), p1 = unpack2(acc[i][1]);
        float2 p2 = unpack2(acc[i][2]), p3 = unpack2(acc[i][3]);
        *(float4*)dst = make_float4(p0.x + bv[0], p0.y + bv[1],
                                    p1.x + bv[2], p1.y + bv[3]);
        *(float4*)(dst + 4) = make_float4(p2.x + bv[4], p2.y + bv[5],
                                          p3.x + bv[6], p3.y + bv[7]);
    }
}

// ---------------- sorted top-16 parallel shift-insert --------------------------
// vals ascending; vals[0] is the running 16th-largest. Strict '<' keeps earlier
// (lower-index) keys on ties, matching lax.top_k.
__device__ __forceinline__ void topk_insert(float (&vals)[TOPK], int (&inds)[TOPK],
                                            float s, int key) {
    bool c[TOPK];
#pragma unroll
    for (int t = 0; t < TOPK; t++) c[t] = vals[t] < s;
#pragma unroll
    for (int t = 0; t < TOPK - 1; t++) {
        vals[t] = c[t + 1] ? vals[t + 1] : (c[t] ? s : vals[t]);
        inds[t] = c[t + 1] ? inds[t + 1] : (c[t] ? key : inds[t]);
    }
    vals[TOPK - 1] = c[TOPK - 1] ? s : vals[TOPK - 1];
    inds[TOPK - 1] = c[TOPK - 1] ? key : inds[TOPK - 1];
}

// ---------------- K3a: routing logits + partial top-16 (split-K over keys) -----
// EXACT R11 structure (proven rel_err 3.633e-7) with KSPLIT widened 2 -> 4:
// same total logit math, but 2048 half-duration blocks instead of 1024 —
// makespan drops from 3 to 2.5 wave-times at ~456 concurrent blocks (wave-
// quantization fix). One thread = one query over 512 keys; 4 keys per group,
// k-loads chunked 2 p-steps (8 LDS.128 live); exact divergent insert.
__global__ void __launch_bounds__(128, 3) route_part_kernel() {
    __shared__ __align__(16) float ks[64 * DHEAD];   // 16 KB key tile

    int bx = blockIdx.x;
    int b   = bx >> 6;          // head-batch 0..31 (64 blocks per bh)
    int ksp = (bx >> 4) & 3;    // key split 0..3
    int qt  = bx & 15;          // query tile
    int tid = threadIdx.x;
    int m = qt * 128 + tid;

    const float scale = 0.04419417382415922f;        // 512^-0.5

    const float* qrow = g_q + ((size_t)(b * MSEQ + m)) * DHEAD;
    unsigned long long qp[32];
#pragma unroll
    for (int d4 = 0; d4 < 16; d4++) {
        float4 t = ((const float4*)qrow)[d4];
        qp[2 * d4]     = pack2(t.x * scale, t.y * scale);
        qp[2 * d4 + 1] = pack2(t.z * scale, t.w * scale);
    }

    float vals[TOPK];
    int   inds[TOPK];
#pragma unroll
    for (int t = 0; t < TOPK; t++) { vals[t] = -CUDART_INF_F; inds[t] = 0; }

    const float* kbase = g_k + (size_t)b * MSEQ * DHEAD + (size_t)ksp * KSEG * DHEAD;

    for (int kt = 0; kt < KSEG / 64; kt++) {
        const float4* src = (const float4*)(kbase + (size_t)kt * 64 * DHEAD);
#pragma unroll
        for (int u = 0; u < 8; u++)
            ((float4*)ks)[tid + u * 128] = src[tid + u * 128];
        __syncthreads();

#pragma unroll 1
        for (int j = 0; j < 64; j += 4) {
            const ulonglong2* kr0 = (const ulonglong2*)(ks + (j + 0) * DHEAD);
            const ulonglong2* kr1 = (const ulonglong2*)(ks + (j + 1) * DHEAD);
            const ulonglong2* kr2 = (const ulonglong2*)(ks + (j + 2) * DHEAD);
            const ulonglong2* kr3 = (const ulonglong2*)(ks + (j + 3) * DHEAD);
            unsigned long long a0 = 0ull, a1 = 0ull, a2 = 0ull, a3 = 0ull;
            unsigned long long b0 = 0ull, b1 = 0ull, b2 = 0ull, b3 = 0ull;
            // 8 chunks of 2 p-steps: per chunk 8 LDS.128 live + 16 FFMA2
#pragma unroll
            for (int pc = 0; pc < 16; pc += 2) {
                ulonglong2 k00 = kr0[pc], k01 = kr0[pc + 1];
                ulonglong2 k10 = kr1[pc], k11 = kr1[pc + 1];
                ulonglong2 k20 = kr2[pc], k21 = kr2[pc + 1];
                ulonglong2 k30 = kr3[pc], k31 = kr3[pc + 1];
                unsigned long long q0 = qp[2 * pc],     q1 = qp[2 * pc + 1];
                unsigned long long q2 = qp[2 * pc + 2], q3 = qp[2 * pc + 3];
                a0 = ffma2(q0, k00.x, a0); b0 = ffma2(q1, k00.y, b0);
                a0 = ffma2(q2, k01.x, a0); b0 = ffma2(q3, k01.y, b0);
                a1 = ffma2(q0, k10.x, a1); b1 = ffma2(q1, k10.y, b1);
                a1 = ffma2(q2, k11.x, a1); b1 = ffma2(q3, k11.y, b1);
                a2 = ffma2(q0, k20.x, a2); b2 = ffma2(q1, k20.y, b2);
                a2 = ffma2(q2, k21.x, a2); b2 = ffma2(q3, k21.y, b2);
                a3 = ffma2(q0, k30.x, a3); b3 = ffma2(q1, k30.y, b3);
                a3 = ffma2(q2, k31.x, a3); b3 = ffma2(q3, k31.y, b3);
            }
            float2 f0 = unpack2(fadd2(a0, b0));
            float2 f1 = unpack2(fadd2(a1, b1));
            float2 f2 = unpack2(fadd2(a2, b2));
            float2 f3 = unpack2(fadd2(a3, b3));
            float s0 = f0.x + f0.y, s1 = f1.x + f1.y;
            float s2 = f2.x + f2.y, s3 = f3.x + f3.y;

            float smax = fmaxf(fmaxf(s0, s1), fmaxf(s2, s3));
            if (smax > vals[0]) {
                int key = kt * 64 + j;
                if (s0 > vals[0]) topk_insert(vals, inds, s0, key);
                if (s1 > vals[0]) topk_insert(vals, inds, s1, key + 1);
                if (s2 > vals[0]) topk_insert(vals, inds, s2, key + 2);
                if (s3 > vals[0]) topk_insert(vals, inds, s3, key + 3);
            }
        }
        __syncthreads();
    }

    size_t base = ((size_t)(b * MSEQ + m) * KSPLIT + ksp) * TOPK;
    int koff = ksp * KSEG;
#pragma unroll
    for (int t = 0; t < TOPK; t++) {
        g_pvals[base + t] = vals[t];
        g_pinds[base + t] = inds[t] + koff;   // globalize key index
    }
}

// ---------------- K3b: merge partial top-16s + softmax + V gather --------------
// 4 threads per query; redundant merge/softmax (lane-redundant work is free in
// warp-time), split V gather (16 dims/thread). Splits are disjoint ascending
// key ranges, so inserting splits 1..3 into sorted split 0 with strict '<'
// reproduces global lax.top_k tie semantics exactly.
__global__ void __launch_bounds__(256) merge_attn_kernel() {
    int tid = threadIdx.x;
    int qloc = tid >> 2, sub = tid & 3;
    int g = blockIdx.x * 64 + qloc;              // global query 0..65535
    int b = g >> 11, m = g & 2047;

    size_t base = (size_t)g * (KSPLIT * TOPK);
    float vals[TOPK];
    int   inds[TOPK];
#pragma unroll
    for (int i = 0; i < 4; i++) {                // split 0, sorted ascending
        float4 v = ((const float4*)(g_pvals + base))[i];
        int4   x = ((const int4*)(g_pinds + base))[i];
        vals[4 * i + 0] = v.x; vals[4 * i + 1] = v.y;
        vals[4 * i + 2] = v.z; vals[4 * i + 3] = v.w;
        inds[4 * i + 0] = x.x; inds[4 * i + 1] = x.y;
        inds[4 * i + 2] = x.z; inds[4 * i + 3] = x.w;
    }
#pragma unroll
    for (int s = 1; s < KSPLIT; s++) {           // insert splits 1..3
#pragma unroll
        for (int i = 0; i < 4; i++) {
            float4 v = ((const float4*)(g_pvals + base + s * TOPK))[i];
            int4   x = ((const int4*)(g_pinds + base + s * TOPK))[i];
            topk_insert(vals, inds, v.x, x.x);
            topk_insert(vals, inds, v.y, x.y);
            topk_insert(vals, inds, v.z, x.z);
            topk_insert(vals, inds, v.w, x.w);
        }
    }

    float mx = vals[TOPK - 1];                   // sorted: last is max
    float w[TOPK];
    float sum = 0.f;
#pragma unroll
    for (int t = 0; t < TOPK; t++) { w[t] = expf(vals[t] - mx); sum += w[t]; }
    float inv = 1.f / sum;

    unsigned long long o[8];
#pragma unroll
    for (int p = 0; p < 8; p++) o[p] = 0ull;

    const float* vbase = g_v + (size_t)b * MSEQ * DHEAD + sub * 16;
#pragma unroll
    for (int t = 0; t < TOPK; t++) {
        unsigned long long wt = dup2(w[t] * inv);
        const ulonglong2* vr = (const ulonglong2*)(vbase + (size_t)inds[t] * DHEAD);
#pragma unroll
        for (int p = 0; p < 4; p++) {
            ulonglong2 vv = vr[p];
            o[2 * p]     = ffma2(wt, vv.x, o[2 * p]);
            o[2 * p + 1] = ffma2(wt, vv.y, o[2 * p + 1]);
        }
    }

    int n = b >> 3, h = b & 7;
    float* dst = g_attn + ((size_t)(n * MSEQ + m)) * CDIM + h * DHEAD + sub * 16;
#pragma unroll
    for (int p = 0; p < 4; p++) {
        ulonglong2 wv; wv.x = o[2 * p]; wv.y = o[2 * p + 1];
        ((ulonglong2*)dst)[p] = wv;
    }
}

// ---------------- K4: output GEMM, 64x128 tiles, double-buffered ---------------
__global__ void __launch_bounds__(256) sgemm_out_kernel(const float* __restrict__ B,
                                                        const float* __restrict__ bias,
                                                        float* __restrict__ Cout) {
    constexpr int NDIM = CDIM;
    __shared__ __align__(16) float As[2][16][64];
    __shared__ __align__(16) float Bs[2][16][128];

    int tid = threadIdx.x;
    int bm = blockIdx.y, bn = blockIdx.x;
    int rowBase = (tid >> 4) << 2;
    int colBase = (tid & 15) << 3;

    int ar = tid >> 2, ak = (tid & 3) << 2;
    int br = tid >> 5, bc = (tid & 31) << 2;

    const float* Ap = g_attn + ((size_t)(bm * 64)) * CDIM;
    const float* Bp = B + bn * 128;

    float4 a0 = *(const float4*)(Ap + (size_t)ar * CDIM + ak);
    float4 b0 = *(const float4*)(Bp + (size_t)br * NDIM + bc);
    float4 b1 = *(const float4*)(Bp + (size_t)(br + 8) * NDIM + bc);
    As[0][ak + 0][ar] = a0.x; As[0][ak + 1][ar] = a0.y;
    As[0][ak + 2][ar] = a0.z; As[0][ak + 3][ar] = a0.w;
    *(float4*)&Bs[0][br][bc] = b0;
    *(float4*)&Bs[0][br + 8][bc] = b1;
    __syncthreads();

    unsigned long long acc[4][4];
#pragma unroll
    for (int i = 0; i < 4; i++)
#pragma unroll
        for (int j = 0; j < 4; j++) acc[i][j] = 0ull;

#pragma unroll 1
    for (int kt = 0; kt < 31; kt++) {
        int cur = kt & 1, nxt = cur ^ 1;
        const float* Ak = Ap + (kt + 1) * 16;
        a0 = *(const float4*)(Ak + (size_t)ar * CDIM + ak);
        const float* Bk = Bp + (size_t)((kt + 1) * 16) * NDIM;
        b0 = *(const float4*)(Bk + (size_t)br * NDIM + bc);
        b1 = *(const float4*)(Bk + (size_t)(br + 8) * NDIM + bc);

#pragma unroll
        for (int k = 0; k < 16; k++) {
            float4 av = *(const float4*)&As[cur][k][rowBase];
            ulonglong2 bv0 = *(const ulonglong2*)&Bs[cur][k][colBase];
            ulonglong2 bv1 = *(const ulonglong2*)&Bs[cur][k][colBase + 4];
            float af[4] = {av.x, av.y, av.z, av.w};
#pragma unroll
            for (int i = 0; i < 4; i++) {
                unsigned long long aa = dup2(af[i]);
                acc[i][0] = ffma2(aa, bv0.x, acc[i][0]);
                acc[i][1] = ffma2(aa, bv0.y, acc[i][1]);
                acc[i][2] = ffma2(aa, bv1.x, acc[i][2]);
                acc[i][3] = ffma2(aa, bv1.y, acc[i][3]);
            }
        }
        As[nxt][ak + 0][ar] = a0.x; As[nxt][ak + 1][ar] = a0.y;
        As[nxt][ak + 2][ar] = a0.z; As[nxt][ak + 3][ar] = a0.w;
        *(float4*)&Bs[nxt][br][bc] = b0;
        *(float4*)&Bs[nxt][br + 8][bc] = b1;
        __syncthreads();
    }
#pragma unroll
    for (int k = 0; k < 16; k++) {
        float4 av = *(const float4*)&As[1][k][rowBase];
        ulonglong2 bv0 = *(const ulonglong2*)&Bs[1][k][colBase];
        ulonglong2 bv1 = *(const ulonglong2*)&Bs[1][k][colBase + 4];
        float af[4] = {av.x, av.y, av.z, av.w};
#pragma unroll
        for (int i = 0; i < 4; i++) {
            unsigned long long aa = dup2(af[i]);
            acc[i][0] = ffma2(aa, bv0.x, acc[i][0]);
            acc[i][1] = ffma2(aa, bv0.y, acc[i][1]);
            acc[i][2] = ffma2(aa, bv1.x, acc[i][2]);
            acc[i][3] = ffma2(aa, bv1.y, acc[i][3]);
        }
    }

    int co0 = bn * 128 + colBase;
    float bv[8];
#pragma unroll
    for (int j = 0; j < 8; j++) bv[j] = bias[co0 + j];
#pragma unroll
    for (int i = 0; i < 4; i++) {
        int r = bm * 64 + rowBase + i;
        float* dst = Cout + (size_t)r * NDIM + co0;
        float2 p0 = unpack2(acc[i][0]), p1 = unpack2(acc[i][1]);
        float2 p2 = unpack2(acc[i][2]), p3 = unpack2(acc[i][3]);
        *(float4*)dst = make_float4(p0.x + bv[0], p0.y + bv[1],
                                    p1.x + bv[2], p1.y + bv[3]);
        *(float4*)(dst + 4) = make_float4(p2.x + bv[4], p2.y + bv[5],
                                          p3.x + bv[6], p3.y + bv[7]);
    }
}

// ---------------- launch ----------------
extern "C" void kernel_launch(void* const* d_in, const int* in_sizes, int n_in,
                              void* d_out, int out_size) {
    (void)in_sizes; (void)n_in; (void)out_size;
    const float* x      = (const float*)d_in[0];
    const float* conv_w = (const float*)d_in[1];
    const float* conv_b = (const float*)d_in[2];
    const float* w_qkv  = (const float*)d_in[3];
    const float* b_qkv  = (const float*)d_in[4];
    const float* w_o    = (const float*)d_in[5];
    const float* b_o    = (const float*)d_in[6];

    profile_shift_dummy_kernel<<<1, 32>>>();                 // #1 (shifts capture)
    conv_res_kernel<<<NB * MSEQ, CDIM>>>(x, conv_w, conv_b); // #2
    sgemm_qkv_kernel<<<dim3(12, 64), 256>>>(w_qkv, b_qkv);   // #3
    route_part_kernel<<<BH * KSPLIT * 16, 128>>>();          // #4 <- ncu window
    merge_attn_kernel<<<1024, 256>>>();                      // #5
    sgemm_out_kernel<<<dim3(4, 128), 256>>>(w_o, b_o, (float*)d_out); // #6
}

// round 17
// speedup vs baseline: 1.0673x; 1.0673x over previous
#include <cuda_runtime.h>
#include <math_constants.h>

#define NB    4
#define MSEQ  2048
#define CDIM  512
#define HNUM  8
#define DHEAD 64
#define TOPK  16
#define BH    (NB * HNUM)   // 32 head-batches
#define KSPLIT 2
#define KSEG   (MSEQ / KSPLIT)  // 1024 keys per split

// route dynamic smem: ks [64][64] f32 (16KB) + Qs2 [32][128] u64 (32KB) = 48KB
#define SMEM_ROUTE (16384 + 32768)

// ---------------- scratch (static device globals; no allocation) ----------------
__device__ float g_xp[NB * MSEQ * CDIM];     // conv+residual output (16 MB)
__device__ float g_q[BH * MSEQ * DHEAD];     // per-head Q
__device__ float g_k[BH * MSEQ * DHEAD];     // per-head K
__device__ float g_v[BH * MSEQ * DHEAD];     // per-head V
__device__ float g_attn[NB * MSEQ * CDIM];   // attention output, (n,m,c) layout
__device__ float g_pvals[BH * MSEQ * KSPLIT * TOPK];  // partial top-k vals (sorted asc)
__device__ int   g_pinds[BH * MSEQ * KSPLIT * TOPK];  // partial top-k global key idx

// ---------------- packed f32x2 helpers (FFMA2: 2x fp32 throughput, sm_103a) ----
__device__ __forceinline__ unsigned long long ffma2(unsigned long long a,
                                                    unsigned long long b,
                                                    unsigned long long c) {
    unsigned long long d;
    asm("fma.rn.f32x2 %0, %1, %2, %3;" : "=l"(d) : "l"(a), "l"(b), "l"(c));
    return d;
}
__device__ __forceinline__ unsigned long long fadd2(unsigned long long a,
                                                    unsigned long long b) {
    unsigned long long d;
    asm("add.rn.f32x2 %0, %1, %2;" : "=l"(d) : "l"(a), "l"(b));
    return d;
}
__device__ __forceinline__ unsigned long long pack2(float lo, float hi) {
    unsigned long long r;
    asm("mov.b64 %0, {%1, %2};" : "=l"(r) : "f"(lo), "f"(hi));
    return r;
}
__device__ __forceinline__ unsigned long long dup2(float a) {
    unsigned long long r;
    asm("mov.b64 %0, {%1, %1};" : "=l"(r) : "f"(a));
    return r;
}
__device__ __forceinline__ float2 unpack2(unsigned long long v) {
    float2 f;
    asm("mov.b64 {%0, %1}, %2;" : "=f"(f.x), "=f"(f.y) : "l"(v));
    return f;
}

// ---------------- K0: dummy — keeps the ncu capture window (4th launch) on
// route_part_kernel so every round gets route's profile. -----------------------
__global__ void profile_shift_dummy_kernel() {}

// ---------------- K1: depthwise conv (k=3, SAME) + residual --------------------
__global__ void conv_res_kernel(const float* __restrict__ x,
                                const float* __restrict__ w,
                                const float* __restrict__ b) {
    int c = threadIdx.x;
    int m = blockIdx.x & (MSEQ - 1);
    int n = blockIdx.x >> 11;
    const float* base = x + ((size_t)(n * MSEQ + m)) * CDIM + c;
    float xc = base[0];
    float xl = (m > 0)        ? base[-CDIM] : 0.f;
    float xr = (m < MSEQ - 1) ? base[ CDIM] : 0.f;
    float w0 = w[3 * c], w1 = w[3 * c + 1], w2 = w[3 * c + 2];
    g_xp[((size_t)(n * MSEQ + m)) * CDIM + c] =
        xc + w0 * xl + w1 * xc + w2 * xr + b[c];
}

// ---------------- K2: QKV GEMM, 128x128 tiles, double-buffered -----------------
__global__ void __launch_bounds__(256) sgemm_qkv_kernel(const float* __restrict__ B,
                                                        const float* __restrict__ bias) {
    constexpr int NDIM = 3 * CDIM;
    __shared__ __align__(16) float As[2][16][128];
    __shared__ __align__(16) float Bs[2][16][128];

    int tid = threadIdx.x;
    int bm = blockIdx.y, bn = blockIdx.x;
    int rowBase = (tid >> 4) << 3;
    int colBase = (tid & 15) << 3;

    int ar = tid >> 2, ak = (tid & 3) << 2;
    int br = tid >> 5, bc = (tid & 31) << 2;

    const float* Ap = g_xp + ((size_t)(bm * 128)) * CDIM;
    const float* Bp = B + bn * 128;

    float4 a0 = *(const float4*)(Ap + (size_t)ar * CDIM + ak);
    float4 a1 = *(const float4*)(Ap + (size_t)(ar + 64) * CDIM + ak);
    float4 b0 = *(const float4*)(Bp + (size_t)br * NDIM + bc);
    float4 b1 = *(const float4*)(Bp + (size_t)(br + 8) * NDIM + bc);

    As[0][ak + 0][ar] = a0.x; As[0][ak + 1][ar] = a0.y;
    As[0][ak + 2][ar] = a0.z; As[0][ak + 3][ar] = a0.w;
    As[0][ak + 0][ar + 64] = a1.x; As[0][ak + 1][ar + 64] = a1.y;
    As[0][ak + 2][ar + 64] = a1.z; As[0][ak + 3][ar + 64] = a1.w;
    *(float4*)&Bs[0][br][bc] = b0;
    *(float4*)&Bs[0][br + 8][bc] = b1;
    __syncthreads();

    unsigned long long acc[8][4];
#pragma unroll
    for (int i = 0; i < 8; i++)
#pragma unroll
        for (int j = 0; j < 4; j++) acc[i][j] = 0ull;

#pragma unroll 1
    for (int kt = 0; kt < 31; kt++) {
        int cur = kt & 1, nxt = cur ^ 1;
        const float* Ak = Ap + (kt + 1) * 16;
        a0 = *(const float4*)(Ak + (size_t)ar * CDIM + ak);
        a1 = *(const float4*)(Ak + (size_t)(ar + 64) * CDIM + ak);
        const float* Bk = Bp + (size_t)((kt + 1) * 16) * NDIM;
        b0 = *(const float4*)(Bk + (size_t)br * NDIM + bc);
        b1 = *(const float4*)(Bk + (size_t)(br + 8) * NDIM + bc);

#pragma unroll
        for (int k = 0; k < 16; k++) {
            float4 av0 = *(const float4*)&As[cur][k][rowBase];
            float4 av1 = *(const float4*)&As[cur][k][rowBase + 4];
            ulonglong2 bv0 = *(const ulonglong2*)&Bs[cur][k][colBase];
            ulonglong2 bv1 = *(const ulonglong2*)&Bs[cur][k][colBase + 4];
            float af[8] = {av0.x, av0.y, av0.z, av0.w, av1.x, av1.y, av1.z, av1.w};
#pragma unroll
            for (int i = 0; i < 8; i++) {
                unsigned long long aa = dup2(af[i]);
                acc[i][0] = ffma2(aa, bv0.x, acc[i][0]);
                acc[i][1] = ffma2(aa, bv0.y, acc[i][1]);
                acc[i][2] = ffma2(aa, bv1.x, acc[i][2]);
                acc[i][3] = ffma2(aa, bv1.y, acc[i][3]);
            }
        }
        As[nxt][ak + 0][ar] = a0.x; As[nxt][ak + 1][ar] = a0.y;
        As[nxt][ak + 2][ar] = a0.z; As[nxt][ak + 3][ar] = a0.w;
        As[nxt][ak + 0][ar + 64] = a1.x; As[nxt][ak + 1][ar + 64] = a1.y;
        As[nxt][ak + 2][ar + 64] = a1.z; As[nxt][ak + 3][ar + 64] = a1.w;
        *(float4*)&Bs[nxt][br][bc] = b0;
        *(float4*)&Bs[nxt][br + 8][bc] = b1;
        __syncthreads();
    }
#pragma unroll
    for (int k = 0; k < 16; k++) {
        float4 av0 = *(const float4*)&As[1][k][rowBase];
        float4 av1 = *(const float4*)&As[1][k][rowBase + 4];
        ulonglong2 bv0 = *(const ulonglong2*)&Bs[1][k][colBase];
        ulonglong2 bv1 = *(const ulonglong2*)&Bs[1][k][colBase + 4];
        float af[8] = {av0.x, av0.y, av0.z, av0.w, av1.x, av1.y, av1.z, av1.w};
#pragma unroll
        for (int i = 0; i < 8; i++) {
            unsigned long long aa = dup2(af[i]);
            acc[i][0] = ffma2(aa, bv0.x, acc[i][0]);
            acc[i][1] = ffma2(aa, bv0.y, acc[i][1]);
            acc[i][2] = ffma2(aa, bv1.x, acc[i][2]);
            acc[i][3] = ffma2(aa, bv1.y, acc[i][3]);
        }
    }

    int co0 = bn * 128 + colBase;
    float bv[8];
#pragma unroll
    for (int j = 0; j < 8; j++) bv[j] = bias[co0 + j];

    int sec = co0 >> 9;            // 0:q 1:k 2:v
    int c2 = co0 & 511;
    int h = c2 >> 6, dd = c2 & 63;
    float* dstbuf = (sec == 0) ? g_q : (sec == 1) ? g_k : g_v;
#pragma unroll
    for (int i = 0; i < 8; i++) {
        int r = bm * 128 + rowBase + i;
        int n = r >> 11, mm = r & 2047;
        float* dst = dstbuf + ((size_t)((n * HNUM + h) * MSEQ + mm)) * DHEAD + dd;
        float2 p0 = unpack2(acc[i][0]), p1 = unpack2(acc[i][1]);
        float2 p2 = unpack2(acc[i][2]), p3 = unpack2(acc[i][3]);
        *(float4*)dst = make_float4(p0.x + bv[0], p0.y + bv[1],
                                    p1.x + bv[2], p1.y + bv[3]);
        *(float4*)(dst + 4) = make_float4(p2.x + bv[4], p2.y + bv[5],
                                          p3.x + bv[6], p3.y + bv[7]);
    }
}

// ---------------- sorted top-16 parallel shift-insert --------------------------
// vals ascending; vals[0] is the running 16th-largest. Strict '<' keeps earlier
// (lower-index) keys on ties, matching lax.top_k.
__device__ __forceinline__ void topk_insert(float (&vals)[TOPK], int (&inds)[TOPK],
                                            float s, int key) {
    bool c[TOPK];
#pragma unroll
    for (int t = 0; t < TOPK; t++) c[t] = vals[t] < s;
#pragma unroll
    for (int t = 0; t < TOPK - 1; t++) {
        vals[t] = c[t + 1] ? vals[t + 1] : (c[t] ? s : vals[t]);
        inds[t] = c[t + 1] ? inds[t + 1] : (c[t] ? key : inds[t]);
    }
    vals[TOPK - 1] = c[TOPK - 1] ? s : vals[TOPK - 1];
    inds[TOPK - 1] = c[TOPK - 1] ? key : inds[TOPK - 1];
}

// ---------------- K3a: routing logits + partial top-16 (split-K over keys) -----
// R11-exact structure (proven rel_err 3.633057e-7) with two profile-driven
// changes from the R16 ncu capture (alu=51.5% > fma=28%, occ=17.7%):
//  (1) KSPLIT back to 2 — insert events scale KSPLIT*(16 + 16*ln(Nsplit/16)):
//      165/query at KSPLIT=2 vs 286 at KSPLIT=4 (the R16 regression).
//  (2) qp[32] (64 regs) moved to per-thread smem Qs2[d2][tid] — thread writes
//      and reads ONLY its own slots (no sync; consecutive-lane u64 LDS.64 is
//      conflict-free; values bit-identical, so logits stay bit-exact). regs
//      165 -> ~110 => 4 blocks/SM (occ 17.7% -> 25%) to fill issue holes.
__global__ void __launch_bounds__(128, 4) route_part_kernel() {
    extern __shared__ __align__(16) char rsm[];
    float* ks = (float*)rsm;                                       // [64][64]
    unsigned long long* Qs2 = (unsigned long long*)(rsm + 16384);  // [32][128]

    int bx = blockIdx.x;
    int b   = bx >> 5;          // head-batch 0..31 (32 blocks per bh)
    int ksp = (bx >> 4) & 1;    // key split 0/1
    int qt  = bx & 15;          // query tile
    int tid = threadIdx.x;
    int m = qt * 128 + tid;

    const float scale = 0.04419417382415922f;        // 512^-0.5

    // per-thread "register spill" of scaled packed Q into smem (own slots only)
    {
        const float* qrow = g_q + ((size_t)(b * MSEQ + m)) * DHEAD;
#pragma unroll
        for (int d4 = 0; d4 < 16; d4++) {
            float4 t = ((const float4*)qrow)[d4];
            Qs2[(2 * d4 + 0) * 128 + tid] = pack2(t.x * scale, t.y * scale);
            Qs2[(2 * d4 + 1) * 128 + tid] = pack2(t.z * scale, t.w * scale);
        }
    }

    float vals[TOPK];
    int   inds[TOPK];
#pragma unroll
    for (int t = 0; t < TOPK; t++) { vals[t] = -CUDART_INF_F; inds[t] = 0; }

    const float* kbase = g_k + (size_t)b * MSEQ * DHEAD + (size_t)ksp * KSEG * DHEAD;

    for (int kt = 0; kt < KSEG / 64; kt++) {
        const float4* src = (const float4*)(kbase + (size_t)kt * 64 * DHEAD);
#pragma unroll
        for (int u = 0; u < 8; u++)
            ((float4*)ks)[tid + u * 128] = src[tid + u * 128];
        __syncthreads();

#pragma unroll 1
        for (int j = 0; j < 64; j += 4) {
            const ulonglong2* kr0 = (const ulonglong2*)(ks + (j + 0) * DHEAD);
            const ulonglong2* kr1 = (const ulonglong2*)(ks + (j + 1) * DHEAD);
            const ulonglong2* kr2 = (const ulonglong2*)(ks + (j + 2) * DHEAD);
            const ulonglong2* kr3 = (const ulonglong2*)(ks + (j + 3) * DHEAD);
            unsigned long long a0 = 0ull, a1 = 0ull, a2 = 0ull, a3 = 0ull;
            unsigned long long b0 = 0ull, b1 = 0ull, b2 = 0ull, b3 = 0ull;
            // 8 chunks of 2 p-steps: 8 broadcast LDS.128 (K) + 4 LDS.64 (Q)
            // feed 16 FFMA2 per chunk
#pragma unroll
            for (int pc = 0; pc < 16; pc += 2) {
                ulonglong2 k00 = kr0[pc], k01 = kr0[pc + 1];
                ulonglong2 k10 = kr1[pc], k11 = kr1[pc + 1];
                ulonglong2 k20 = kr2[pc], k21 = kr2[pc + 1];
                ulonglong2 k30 = kr3[pc], k31 = kr3[pc + 1];
                unsigned long long q0 = Qs2[(2 * pc + 0) * 128 + tid];
                unsigned long long q1 = Qs2[(2 * pc + 1) * 128 + tid];
                unsigned long long q2 = Qs2[(2 * pc + 2) * 128 + tid];
                unsigned long long q3 = Qs2[(2 * pc + 3) * 128 + tid];
                a0 = ffma2(q0, k00.x, a0); b0 = ffma2(q1, k00.y, b0);
                a0 = ffma2(q2, k01.x, a0); b0 = ffma2(q3, k01.y, b0);
                a1 = ffma2(q0, k10.x, a1); b1 = ffma2(q1, k10.y, b1);
                a1 = ffma2(q2, k11.x, a1); b1 = ffma2(q3, k11.y, b1);
                a2 = ffma2(q0, k20.x, a2); b2 = ffma2(q1, k20.y, b2);
                a2 = ffma2(q2, k21.x, a2); b2 = ffma2(q3, k21.y, b2);
                a3 = ffma2(q0, k30.x, a3); b3 = ffma2(q1, k30.y, b3);
                a3 = ffma2(q2, k31.x, a3); b3 = ffma2(q3, k31.y, b3);
            }
            float2 f0 = unpack2(fadd2(a0, b0));
            float2 f1 = unpack2(fadd2(a1, b1));
            float2 f2 = unpack2(fadd2(a2, b2));
            float2 f3 = unpack2(fadd2(a3, b3));
            float s0 = f0.x + f0.y, s1 = f1.x + f1.y;
            float s2 = f2.x + f2.y, s3 = f3.x + f3.y;

            float smax = fmaxf(fmaxf(s0, s1), fmaxf(s2, s3));
            if (smax > vals[0]) {
                int key = kt * 64 + j;
                if (s0 > vals[0]) topk_insert(vals, inds, s0, key);
                if (s1 > vals[0]) topk_insert(vals, inds, s1, key + 1);
                if (s2 > vals[0]) topk_insert(vals, inds, s2, key + 2);
                if (s3 > vals[0]) topk_insert(vals, inds, s3, key + 3);
            }
        }
        __syncthreads();
    }

    size_t base = ((size_t)(b * MSEQ + m) * KSPLIT + ksp) * TOPK;
    int koff = ksp * KSEG;
#pragma unroll
    for (int t = 0; t < TOPK; t++) {
        g_pvals[base + t] = vals[t];
        g_pinds[base + t] = inds[t] + koff;   // globalize key index
    }
}

// ---------------- K3b: merge partial top-16s + softmax + V gather --------------
// 4 threads per query; redundant merge/softmax, split V gather (16 dims/thread).
// Splits are disjoint ascending key ranges, so inserting split 1 into sorted
// split 0 with strict '<' reproduces global lax.top_k tie semantics exactly.
__global__ void __launch_bounds__(256) merge_attn_kernel() {
    int tid = threadIdx.x;
    int qloc = tid >> 2, sub = tid & 3;
    int g = blockIdx.x * 64 + qloc;              // global query 0..65535
    int b = g >> 11, m = g & 2047;

    size_t base = (size_t)g * (KSPLIT * TOPK);
    float vals[TOPK];
    int   inds[TOPK];
#pragma unroll
    for (int i = 0; i < 4; i++) {                // split 0, sorted ascending
        float4 v = ((const float4*)(g_pvals + base))[i];
        int4   x = ((const int4*)(g_pinds + base))[i];
        vals[4 * i + 0] = v.x; vals[4 * i + 1] = v.y;
        vals[4 * i + 2] = v.z; vals[4 * i + 3] = v.w;
        inds[4 * i + 0] = x.x; inds[4 * i + 1] = x.y;
        inds[4 * i + 2] = x.z; inds[4 * i + 3] = x.w;
    }
#pragma unroll
    for (int s = 1; s < KSPLIT; s++) {           // insert remaining splits
#pragma unroll
        for (int i = 0; i < 4; i++) {
            float4 v = ((const float4*)(g_pvals + base + s * TOPK))[i];
            int4   x = ((const int4*)(g_pinds + base + s * TOPK))[i];
            topk_insert(vals, inds, v.x, x.x);
            topk_insert(vals, inds, v.y, x.y);
            topk_insert(vals, inds, v.z, x.z);
            topk_insert(vals, inds, v.w, x.w);
        }
    }

    float mx = vals[TOPK - 1];                   // sorted: last is max
    float w[TOPK];
    float sum = 0.f;
#pragma unroll
    for (int t = 0; t < TOPK; t++) { w[t] = expf(vals[t] - mx); sum += w[t]; }
    float inv = 1.f / sum;

    unsigned long long o[8];
#pragma unroll
    for (int p = 0; p < 8; p++) o[p] = 0ull;

    const float* vbase = g_v + (size_t)b * MSEQ * DHEAD + sub * 16;
#pragma unroll
    for (int t = 0; t < TOPK; t++) {
        unsigned long long wt = dup2(w[t] * inv);
        const ulonglong2* vr = (const ulonglong2*)(vbase + (size_t)inds[t] * DHEAD);
#pragma unroll
        for (int p = 0; p < 4; p++) {
            ulonglong2 vv = vr[p];
            o[2 * p]     = ffma2(wt, vv.x, o[2 * p]);
            o[2 * p + 1] = ffma2(wt, vv.y, o[2 * p + 1]);
        }
    }

    int n = b >> 3, h = b & 7;
    float* dst = g_attn + ((size_t)(n * MSEQ + m)) * CDIM + h * DHEAD + sub * 16;
#pragma unroll
    for (int p = 0; p < 4; p++) {
        ulonglong2 wv; wv.x = o[2 * p]; wv.y = o[2 * p + 1];
        ((ulonglong2*)dst)[p] = wv;
    }
}

// ---------------- K4: output GEMM, 64x128 tiles, double-buffered ---------------
__global__ void __launch_bounds__(256) sgemm_out_kernel(const float* __restrict__ B,
                                                        const float* __restrict__ bias,
                                                        float* __restrict__ Cout) {
    constexpr int NDIM = CDIM;
    __shared__ __align__(16) float As[2][16][64];
    __shared__ __align__(16) float Bs[2][16][128];

    int tid = threadIdx.x;
    int bm = blockIdx.y, bn = blockIdx.x;
    int rowBase = (tid >> 4) << 2;
    int colBase = (tid & 15) << 3;

    int ar = tid >> 2, ak = (tid & 3) << 2;
    int br = tid >> 5, bc = (tid & 31) << 2;

    const float* Ap = g_attn + ((size_t)(bm * 64)) * CDIM;
    const float* Bp = B + bn * 128;

    float4 a0 = *(const float4*)(Ap + (size_t)ar * CDIM + ak);
    float4 b0 = *(const float4*)(Bp + (size_t)br * NDIM + bc);
    float4 b1 = *(const float4*)(Bp + (size_t)(br + 8) * NDIM + bc);
    As[0][ak + 0][ar] = a0.x; As[0][ak + 1][ar] = a0.y;
    As[0][ak + 2][ar] = a0.z; As[0][ak + 3][ar] = a0.w;
    *(float4*)&Bs[0][br][bc] = b0;
    *(float4*)&Bs[0][br + 8][bc] = b1;
    __syncthreads();

    unsigned long long acc[4][4];
#pragma unroll
    for (int i = 0; i < 4; i++)
#pragma unroll
        for (int j = 0; j < 4; j++) acc[i][j] = 0ull;

#pragma unroll 1
    for (int kt = 0; kt < 31; kt++) {
        int cur = kt & 1, nxt = cur ^ 1;
        const float* Ak = Ap + (kt + 1) * 16;
        a0 = *(const float4*)(Ak + (size_t)ar * CDIM + ak);
        const float* Bk = Bp + (size_t)((kt + 1) * 16) * NDIM;
        b0 = *(const float4*)(Bk + (size_t)br * NDIM + bc);
        b1 = *(const float4*)(Bk + (size_t)(br + 8) * NDIM + bc);

#pragma unroll
        for (int k = 0; k < 16; k++) {
            float4 av = *(const float4*)&As[cur][k][rowBase];
            ulonglong2 bv0 = *(const ulonglong2*)&Bs[cur][k][colBase];
            ulonglong2 bv1 = *(const ulonglong2*)&Bs[cur][k][colBase + 4];
            float af[4] = {av.x, av.y, av.z, av.w};
#pragma unroll
            for (int i = 0; i < 4; i++) {
                unsigned long long aa = dup2(af[i]);
                acc[i][0] = ffma2(aa, bv0.x, acc[i][0]);
                acc[i][1] = ffma2(aa, bv0.y, acc[i][1]);
                acc[i][2] = ffma2(aa, bv1.x, acc[i][2]);
                acc[i][3] = ffma2(aa, bv1.y, acc[i][3]);
            }
        }
        As[nxt][ak + 0][ar] = a0.x; As[nxt][ak + 1][ar] = a0.y;
        As[nxt][ak + 2][ar] = a0.z; As[nxt][ak + 3][ar] = a0.w;
        *(float4*)&Bs[nxt][br][bc] = b0;
        *(float4*)&Bs[nxt][br + 8][bc] = b1;
        __syncthreads();
    }
#pragma unroll
    for (int k = 0; k < 16; k++) {
        float4 av = *(const float4*)&As[1][k][rowBase];
        ulonglong2 bv0 = *(const ulonglong2*)&Bs[1][k][colBase];
        ulonglong2 bv1 = *(const ulonglong2*)&Bs[1][k][colBase + 4];
        float af[4] = {av.x, av.y, av.z, av.w};
#pragma unroll
        for (int i = 0; i < 4; i++) {
            unsigned long long aa = dup2(af[i]);
            acc[i][0] = ffma2(aa, bv0.x, acc[i][0]);
            acc[i][1] = ffma2(aa, bv0.y, acc[i][1]);
            acc[i][2] = ffma2(aa, bv1.x, acc[i][2]);
            acc[i][3] = ffma2(aa, bv1.y, acc[i][3]);
        }
    }

    int co0 = bn * 128 + colBase;
    float bv[8];
#pragma unroll
    for (int j = 0; j < 8; j++) bv[j] = bias[co0 + j];
#pragma unroll
    for (int i = 0; i < 4; i++) {
        int r = bm * 64 + rowBase + i;
        float* dst = Cout + (size_t)r * NDIM + co0;
        float2 p0 = unpack2(acc[i][0]), p1 = unpack2(acc[i][1]);
        float2 p2 = unpack2(acc[i][2]), p3 = unpack2(acc[i][3]);
        *(float4*)dst = make_float4(p0.x + bv[0], p0.y + bv[1],
                                    p1.x + bv[2], p1.y + bv[3]);
        *(float4*)(dst + 4) = make_float4(p2.x + bv[4], p2.y + bv[5],
                                          p3.x + bv[6], p3.y + bv[7]);
    }
}

// ---------------- launch ----------------
extern "C" void kernel_launch(void* const* d_in, const int* in_sizes, int n_in,
                              void* d_out, int out_size) {
    (void)in_sizes; (void)n_in; (void)out_size;
    const float* x      = (const float*)d_in[0];
    const float* conv_w = (const float*)d_in[1];
    const float* conv_b = (const float*)d_in[2];
    const float* w_qkv  = (const float*)d_in[3];
    const float* b_qkv  = (const float*)d_in[4];
    const float* w_o    = (const float*)d_in[5];
    const float* b_o    = (const float*)d_in[6];

    cudaFuncSetAttribute(route_part_kernel,
                         cudaFuncAttributeMaxDynamicSharedMemorySize, SMEM_ROUTE);

    profile_shift_dummy_kernel<<<1, 32>>>();                 // #1 (shifts capture)
    conv_res_kernel<<<NB * MSEQ, CDIM>>>(x, conv_w, conv_b); // #2
    sgemm_qkv_kernel<<<dim3(12, 64), 256>>>(w_qkv, b_qkv);   // #3
    route_part_kernel<<<BH * KSPLIT * 16, 128, SMEM_ROUTE>>>(); // #4 <- ncu window
    merge_attn_kernel<<<1024, 256>>>();                      // #5
    sgemm_out_kernel<<<dim3(4, 128), 256>>>(w_o, b_o, (float*)d_out); // #6
}